// round 3
// baseline (speedup 1.0000x reference)
#include <cuda_runtime.h>
#include <math.h>

#define BATCH 2
#define IH 1080
#define IW 1920
#define SH 540
#define SW 960

#define N_SMALL (BATCH * SH * SW)
#define N_FULL  (BATCH * IH * IW)

// sobel pixel shifts (compile-time): offset*(W-1)/W, offset*(H-1)/H
#define SX1 (959.0f / 960.0f)
#define SY1 (539.0f / 540.0f)
#define SX2 (0.5f * 959.0f / 960.0f)
#define SY2 (0.5f * 539.0f / 540.0f)

// Gaussian sigma=1.0, ks=5 weights
#define GW0 0.05448868f
#define GW1 0.24420135f
#define GW2 0.40261995f

// Scratch (allocation-free: __device__ globals)
__device__ float  g_edge[N_SMALL];         // edge magnitude
__device__ float  g_tmp[N_SMALL];          // blurred edge
__device__ float2 g_grad_s[N_SMALL];       // small gradient field (xg, yg)
__device__ float2 g_grad_f[N_FULL];        // upsampled gradient field

__device__ __forceinline__ float clampf(float v, float lo, float hi) {
    return fminf(fmaxf(v, lo), hi);
}

// ---------------------------------------------------------------------------
// Fused: luma + bilinear downscale + sobel(offset=1) edge magnitude.
// Luma tile (with halo 1) in smem, then constant-weight 3x3 stencil.
// ---------------------------------------------------------------------------
#define EBX 32
#define EBY 18
__global__ void k_luma_edge(const float* __restrict__ img, float* __restrict__ out) {
    __shared__ float s[EBY + 2][EBX + 2];
    int b = blockIdx.z;
    int tx0 = blockIdx.x * EBX;
    int ty0 = blockIdx.y * EBY;

    const float* r  = img + ((size_t)b * 3 + 0) * IH * IW;
    const float* g  = img + ((size_t)b * 3 + 1) * IH * IW;
    const float* bl = img + ((size_t)b * 3 + 2) * IH * IW;

    int tid = threadIdx.y * EBX + threadIdx.x;
    const int NLOAD = (EBY + 2) * (EBX + 2);
    for (int idx = tid; idx < NLOAD; idx += EBX * EBY) {
        int lx = idx % (EBX + 2);
        int ly = idx / (EBX + 2);
        int xs = min(max(tx0 - 1 + lx, 0), SW - 1);
        int ys = min(max(ty0 - 1 + ly, 0), SH - 1);
        // downsample position (align_corners): f = small * (big-1)/(small-1)
        float fx = (float)xs * (1919.0f / 959.0f);
        float fy = (float)ys * (1079.0f / 539.0f);
        int x0 = min((int)fx, IW - 1); int x1 = min(x0 + 1, IW - 1);
        int y0 = min((int)fy, IH - 1); int y1 = min(y0 + 1, IH - 1);
        float wx = fx - (float)x0, wy = fy - (float)y0;
        int o00 = y0 * IW + x0, o01 = y0 * IW + x1, o10 = y1 * IW + x0, o11 = y1 * IW + x1;
        float v00 = 0.299f * r[o00] + 0.587f * g[o00] + 0.114f * bl[o00];
        float v01 = 0.299f * r[o01] + 0.587f * g[o01] + 0.114f * bl[o01];
        float v10 = 0.299f * r[o10] + 0.587f * g[o10] + 0.114f * bl[o10];
        float v11 = 0.299f * r[o11] + 0.587f * g[o11] + 0.114f * bl[o11];
        s[ly][lx] = (v00 * (1.0f - wx) + v01 * wx) * (1.0f - wy)
                  + (v10 * (1.0f - wx) + v11 * wx) * wy;
    }
    __syncthreads();

    int lx = threadIdx.x, ly = threadIdx.y;
    float a = s[ly][lx],     bb = s[ly][lx + 1],     c = s[ly][lx + 2];
    float d = s[ly + 1][lx], e  = s[ly + 1][lx + 1], f = s[ly + 1][lx + 2];
    float gg = s[ly + 2][lx], h = s[ly + 2][lx + 1], ii = s[ly + 2][lx + 2];

    float ch0m = SX1 * (c - a), ch0c = SX1 * (f - d), ch0p = SX1 * (ii - gg);
    float xg = 0.125f * (SY1 * (ch0m + ch0p) + (4.0f - 2.0f * SY1) * ch0c);
    float ch1m = SX1 * (a + c) + (4.0f - 2.0f * SX1) * bb;
    float ch1p = SX1 * (gg + ii) + (4.0f - 2.0f * SX1) * h;
    float yg = 0.125f * SY1 * (ch1p - ch1m);

    out[(b * SH + ty0 + ly) * SW + tx0 + lx] = powf(xg * xg + yg * yg, 0.35f);
}

// ---------------------------------------------------------------------------
// Fused separable Gaussian blur (5x5 outer-product, edge replicate)
// ---------------------------------------------------------------------------
#define BBX 32
#define BBY 10
__global__ void k_blur(const float* __restrict__ in, float* __restrict__ out) {
    __shared__ float s[BBY + 4][BBX + 4];
    int b = blockIdx.z;
    int tx0 = blockIdx.x * BBX;
    int ty0 = blockIdx.y * BBY;
    const float* pl = in + b * SH * SW;

    int tid = threadIdx.y * BBX + threadIdx.x;
    const int NLOAD = (BBY + 4) * (BBX + 4);
    for (int idx = tid; idx < NLOAD; idx += BBX * BBY) {
        int lx = idx % (BBX + 4);
        int ly = idx / (BBX + 4);
        int gx = min(max(tx0 - 2 + lx, 0), SW - 1);
        int gy = min(max(ty0 - 2 + ly, 0), SH - 1);
        s[ly][lx] = pl[gy * SW + gx];
    }
    __syncthreads();

    int lx = threadIdx.x, ly = threadIdx.y;
    const float w[5] = {GW0, GW1, GW2, GW1, GW0};
    float acc = 0.0f;
    #pragma unroll
    for (int j = 0; j < 5; ++j) {
        float h = 0.0f;
        #pragma unroll
        for (int ii = 0; ii < 5; ++ii)
            h = fmaf(w[ii], s[ly + j][lx + ii], h);
        acc = fmaf(w[j], h, acc);
    }
    out[(b * SH + ty0 + ly) * SW + tx0 + lx] = acc;
}

// ---------------------------------------------------------------------------
// sobel(offset=0.5) gradient field: constant-weight 3x3 stencil (smem tile)
// ---------------------------------------------------------------------------
__global__ void k_grad(const float* __restrict__ in, float2* __restrict__ out) {
    __shared__ float s[EBY + 2][EBX + 2];
    int b = blockIdx.z;
    int tx0 = blockIdx.x * EBX;
    int ty0 = blockIdx.y * EBY;
    const float* pl = in + b * SH * SW;

    int tid = threadIdx.y * EBX + threadIdx.x;
    const int NLOAD = (EBY + 2) * (EBX + 2);
    for (int idx = tid; idx < NLOAD; idx += EBX * EBY) {
        int lx = idx % (EBX + 2);
        int ly = idx / (EBX + 2);
        int gx = min(max(tx0 - 1 + lx, 0), SW - 1);
        int gy = min(max(ty0 - 1 + ly, 0), SH - 1);
        s[ly][lx] = pl[gy * SW + gx];
    }
    __syncthreads();

    int lx = threadIdx.x, ly = threadIdx.y;
    float a = s[ly][lx],     bb = s[ly][lx + 1],     c = s[ly][lx + 2];
    float d = s[ly + 1][lx],                          f = s[ly + 1][lx + 2];
    float gg = s[ly + 2][lx], h = s[ly + 2][lx + 1], ii = s[ly + 2][lx + 2];

    float ch0m = SX2 * (c - a), ch0c = SX2 * (f - d), ch0p = SX2 * (ii - gg);
    float xg = 0.125f * (SY2 * (ch0m + ch0p) + (4.0f - 2.0f * SY2) * ch0c);
    float ch1m = SX2 * (a + c) + (4.0f - 2.0f * SX2) * bb;
    float ch1p = SX2 * (gg + ii) + (4.0f - 2.0f * SX2) * h;
    float yg = 0.125f * SY2 * (ch1p - ch1m);

    out[(b * SH + ty0 + ly) * SW + tx0 + lx] = make_float2(xg, yg);
}

// ---------------------------------------------------------------------------
// Bilinear upsample grad field 540x960 -> 1080x1920, 4 px/thread
// ---------------------------------------------------------------------------
__global__ void k_upsample(const float2* __restrict__ gs, float2* __restrict__ gf) {
    int i = blockIdx.x * blockDim.x + threadIdx.x;
    const int QW = IW / 4;
    if (i >= BATCH * IH * QW) return;
    int xq = (i % QW) * 4;
    int y  = (i / QW) % IH;
    int b  = i / (QW * IH);

    float fy = (float)y * (539.0f / 1079.0f);
    int y0 = min((int)fy, SH - 1);
    int y1 = min(y0 + 1, SH - 1);
    float wy = fy - (float)y0;

    const float2* p0 = gs + b * SH * SW + y0 * SW;
    const float2* p1 = gs + b * SH * SW + y1 * SW;

    float2 res[4];
    #pragma unroll
    for (int k = 0; k < 4; ++k) {
        int x = xq + k;
        float fx = (float)x * (959.0f / 1919.0f);
        int x0 = min((int)fx, SW - 1);
        int x1 = min(x0 + 1, SW - 1);
        float wx = fx - (float)x0;
        float2 a00 = p0[x0], a01 = p0[x1], a10 = p1[x0], a11 = p1[x1];
        float vx = (a00.x * (1.0f - wx) + a01.x * wx) * (1.0f - wy)
                 + (a10.x * (1.0f - wx) + a11.x * wx) * wy;
        float vy = (a00.y * (1.0f - wx) + a01.y * wx) * (1.0f - wy)
                 + (a10.y * (1.0f - wx) + a11.y * wx) * wy;
        res[k] = make_float2(vx, vy);
    }
    float4* dst = (float4*)(gf + (size_t)(b * IH + y) * IW + xq);
    dst[0] = make_float4(res[0].x, res[0].y, res[1].x, res[1].y);
    dst[1] = make_float4(res[2].x, res[2].y, res[3].x, res[3].y);
}

// ---------------------------------------------------------------------------
// Warp: 6 fixed-point iterations + final image sample. 4 px/thread.
// ---------------------------------------------------------------------------
__global__ void k_warp(const float* __restrict__ img, const float2* __restrict__ gf,
                       float* __restrict__ out) {
    int i = blockIdx.x * blockDim.x + threadIdx.x;
    const int QW = IW / 4;
    if (i >= BATCH * IH * QW) return;
    int Xq = (i % QW) * 4;
    int Y  = (i / QW) % IH;
    int b  = i / (QW * IH);

    const float relstr = ((float)IH / 1080.0f) * 0.1f;
    const float stepx = 2.0f / (float)IW * relstr;
    const float stepy = 2.0f / (float)IH * relstr;

    const float2* g = gf + (size_t)b * IH * IW;

    float px[4], py[4];
    #pragma unroll
    for (int k = 0; k < 4; ++k) {
        px[k] = -1.0f + 2.0f * (float)(Xq + k) / (float)(IW - 1);
        py[k] = -1.0f + 2.0f * (float)Y / (float)(IH - 1);
    }

    #pragma unroll
    for (int it = 0; it < 6; ++it) {
        #pragma unroll
        for (int k = 0; k < 4; ++k) {
            float fx = clampf((px[k] + 1.0f) * 0.5f * (float)(IW - 1), 0.0f, (float)(IW - 1));
            float fy = clampf((py[k] + 1.0f) * 0.5f * (float)(IH - 1), 0.0f, (float)(IH - 1));
            int x0 = (int)fx, y0 = (int)fy;
            int x1 = min(x0 + 1, IW - 1), y1 = min(y0 + 1, IH - 1);
            float wx = fx - (float)x0, wy = fy - (float)y0;

            float2 a00 = g[y0 * IW + x0], a01 = g[y0 * IW + x1];
            float2 a10 = g[y1 * IW + x0], a11 = g[y1 * IW + x1];
            float dx = (a00.x * (1.0f - wx) + a01.x * wx) * (1.0f - wy)
                     + (a10.x * (1.0f - wx) + a11.x * wx) * wy;
            float dy = (a00.y * (1.0f - wx) + a01.y * wx) * (1.0f - wy)
                     + (a10.y * (1.0f - wx) + a11.y * wx) * wy;

            float len = sqrtf(dx * dx + dy * dy) + 0.01f;
            float inv = __fdividef(1.0f, len);
            px[k] -= dx * inv * stepx;
            py[k] -= dy * inv * stepy;
        }
    }

    int o00[4], o01[4], o10[4], o11[4];
    float wx[4], wy[4];
    #pragma unroll
    for (int k = 0; k < 4; ++k) {
        float fx = clampf((px[k] + 1.0f) * 0.5f * (float)(IW - 1), 0.0f, (float)(IW - 1));
        float fy = clampf((py[k] + 1.0f) * 0.5f * (float)(IH - 1), 0.0f, (float)(IH - 1));
        int x0 = (int)fx, y0 = (int)fy;
        int x1 = min(x0 + 1, IW - 1), y1 = min(y0 + 1, IH - 1);
        wx[k] = fx - (float)x0; wy[k] = fy - (float)y0;
        o00[k] = y0 * IW + x0; o01[k] = y0 * IW + x1;
        o10[k] = y1 * IW + x0; o11[k] = y1 * IW + x1;
    }

    #pragma unroll
    for (int c = 0; c < 3; ++c) {
        const float* p = img + ((size_t)b * 3 + c) * IH * IW;
        float v[4];
        #pragma unroll
        for (int k = 0; k < 4; ++k) {
            float vv = (p[o00[k]] * (1.0f - wx[k]) + p[o01[k]] * wx[k]) * (1.0f - wy[k])
                     + (p[o10[k]] * (1.0f - wx[k]) + p[o11[k]] * wx[k]) * wy[k];
            v[k] = clampf(vv, 0.0f, 1.0f);
        }
        float4* dst = (float4*)(out + ((size_t)b * 3 + c) * IH * IW + (size_t)Y * IW + Xq);
        *dst = make_float4(v[0], v[1], v[2], v[3]);
    }
}

// ---------------------------------------------------------------------------
extern "C" void kernel_launch(void* const* d_in, const int* in_sizes, int n_in,
                              void* d_out, int out_size) {
    const float* img = (const float*)d_in[0];
    float* out = (float*)d_out;

    float *p_edge, *p_tmp;
    float2 *p_grad_s, *p_grad_f;
    cudaGetSymbolAddress((void**)&p_edge, g_edge);
    cudaGetSymbolAddress((void**)&p_tmp, g_tmp);
    cudaGetSymbolAddress((void**)&p_grad_s, g_grad_s);
    cudaGetSymbolAddress((void**)&p_grad_f, g_grad_f);

    dim3 eb(EBX, EBY);
    dim3 eg(SW / EBX, SH / EBY, BATCH);       // 30 x 30 x 2
    k_luma_edge<<<eg, eb>>>(img, p_edge);

    dim3 bb(BBX, BBY);
    dim3 gb(SW / BBX, SH / BBY, BATCH);
    k_blur<<<gb, bb>>>(p_edge, p_tmp);

    k_grad<<<eg, eb>>>(p_tmp, p_grad_s);

    const int T = 256;
    int gq = (BATCH * IH * (IW / 4) + T - 1) / T;
    k_upsample<<<gq, T>>>(p_grad_s, p_grad_f);
    k_warp<<<gq, T>>>(img, p_grad_f, out);
}

// round 4
// speedup vs baseline: 1.1969x; 1.1969x over previous
#include <cuda_runtime.h>
#include <cuda_fp16.h>
#include <math.h>

#define BATCH 2
#define IH 1080
#define IW 1920
#define SH 540
#define SW 960

#define N_SMALL (BATCH * SH * SW)
#define N_FULL  (BATCH * IH * IW)

// sobel pixel shifts (compile-time): offset*(W-1)/W, offset*(H-1)/H
#define SX1 (959.0f / 960.0f)
#define SY1 (539.0f / 540.0f)
#define SX2 (0.5f * 959.0f / 960.0f)
#define SY2 (0.5f * 539.0f / 540.0f)

// Gaussian sigma=1.0, ks=5 weights
#define GW0 0.05448868f
#define GW1 0.24420135f
#define GW2 0.40261995f

// Scratch (allocation-free: __device__ globals)
__device__ float   g_edge[N_SMALL];        // edge magnitude
__device__ float   g_tmp[N_SMALL];         // blurred edge
__device__ float2  g_grad_s[N_SMALL];      // small gradient field (xg, yg) fp32
__device__ __half2 g_grad_f[N_FULL];       // upsampled gradient field, half2 (xg, yg)

__device__ __forceinline__ float clampf(float v, float lo, float hi) {
    return fminf(fmaxf(v, lo), hi);
}

// ---------------------------------------------------------------------------
// Fused: luma + bilinear downscale + sobel(offset=1) edge magnitude.
// ---------------------------------------------------------------------------
#define EBX 32
#define EBY 18
__global__ void k_luma_edge(const float* __restrict__ img, float* __restrict__ out) {
    __shared__ float s[EBY + 2][EBX + 2];
    int b = blockIdx.z;
    int tx0 = blockIdx.x * EBX;
    int ty0 = blockIdx.y * EBY;

    const float* r  = img + ((size_t)b * 3 + 0) * IH * IW;
    const float* g  = img + ((size_t)b * 3 + 1) * IH * IW;
    const float* bl = img + ((size_t)b * 3 + 2) * IH * IW;

    int tid = threadIdx.y * EBX + threadIdx.x;
    const int NLOAD = (EBY + 2) * (EBX + 2);
    for (int idx = tid; idx < NLOAD; idx += EBX * EBY) {
        int lx = idx % (EBX + 2);
        int ly = idx / (EBX + 2);
        int xs = min(max(tx0 - 1 + lx, 0), SW - 1);
        int ys = min(max(ty0 - 1 + ly, 0), SH - 1);
        float fx = (float)xs * (1919.0f / 959.0f);
        float fy = (float)ys * (1079.0f / 539.0f);
        int x0 = min((int)fx, IW - 1); int x1 = min(x0 + 1, IW - 1);
        int y0 = min((int)fy, IH - 1); int y1 = min(y0 + 1, IH - 1);
        float wx = fx - (float)x0, wy = fy - (float)y0;
        int o00 = y0 * IW + x0, o01 = y0 * IW + x1, o10 = y1 * IW + x0, o11 = y1 * IW + x1;
        float v00 = 0.299f * r[o00] + 0.587f * g[o00] + 0.114f * bl[o00];
        float v01 = 0.299f * r[o01] + 0.587f * g[o01] + 0.114f * bl[o01];
        float v10 = 0.299f * r[o10] + 0.587f * g[o10] + 0.114f * bl[o10];
        float v11 = 0.299f * r[o11] + 0.587f * g[o11] + 0.114f * bl[o11];
        s[ly][lx] = (v00 * (1.0f - wx) + v01 * wx) * (1.0f - wy)
                  + (v10 * (1.0f - wx) + v11 * wx) * wy;
    }
    __syncthreads();

    int lx = threadIdx.x, ly = threadIdx.y;
    float a = s[ly][lx],     bb = s[ly][lx + 1],     c = s[ly][lx + 2];
    float d = s[ly + 1][lx],                          f = s[ly + 1][lx + 2];
    float gg = s[ly + 2][lx], h = s[ly + 2][lx + 1], ii = s[ly + 2][lx + 2];

    float ch0m = SX1 * (c - a), ch0c = SX1 * (f - d), ch0p = SX1 * (ii - gg);
    float xg = 0.125f * (SY1 * (ch0m + ch0p) + (4.0f - 2.0f * SY1) * ch0c);
    float ch1m = SX1 * (a + c) + (4.0f - 2.0f * SX1) * bb;
    float ch1p = SX1 * (gg + ii) + (4.0f - 2.0f * SX1) * h;
    float yg = 0.125f * SY1 * (ch1p - ch1m);

    out[(b * SH + ty0 + ly) * SW + tx0 + lx] = powf(xg * xg + yg * yg, 0.35f);
}

// ---------------------------------------------------------------------------
// Fused separable Gaussian blur (5x5 outer-product, edge replicate)
// ---------------------------------------------------------------------------
#define BBX 32
#define BBY 10
__global__ void k_blur(const float* __restrict__ in, float* __restrict__ out) {
    __shared__ float s[BBY + 4][BBX + 4];
    int b = blockIdx.z;
    int tx0 = blockIdx.x * BBX;
    int ty0 = blockIdx.y * BBY;
    const float* pl = in + b * SH * SW;

    int tid = threadIdx.y * BBX + threadIdx.x;
    const int NLOAD = (BBY + 4) * (BBX + 4);
    for (int idx = tid; idx < NLOAD; idx += BBX * BBY) {
        int lx = idx % (BBX + 4);
        int ly = idx / (BBX + 4);
        int gx = min(max(tx0 - 2 + lx, 0), SW - 1);
        int gy = min(max(ty0 - 2 + ly, 0), SH - 1);
        s[ly][lx] = pl[gy * SW + gx];
    }
    __syncthreads();

    int lx = threadIdx.x, ly = threadIdx.y;
    const float w[5] = {GW0, GW1, GW2, GW1, GW0};
    float acc = 0.0f;
    #pragma unroll
    for (int j = 0; j < 5; ++j) {
        float h = 0.0f;
        #pragma unroll
        for (int ii = 0; ii < 5; ++ii)
            h = fmaf(w[ii], s[ly + j][lx + ii], h);
        acc = fmaf(w[j], h, acc);
    }
    out[(b * SH + ty0 + ly) * SW + tx0 + lx] = acc;
}

// ---------------------------------------------------------------------------
// sobel(offset=0.5) gradient field: constant-weight 3x3 stencil (smem tile)
// ---------------------------------------------------------------------------
__global__ void k_grad(const float* __restrict__ in, float2* __restrict__ out) {
    __shared__ float s[EBY + 2][EBX + 2];
    int b = blockIdx.z;
    int tx0 = blockIdx.x * EBX;
    int ty0 = blockIdx.y * EBY;
    const float* pl = in + b * SH * SW;

    int tid = threadIdx.y * EBX + threadIdx.x;
    const int NLOAD = (EBY + 2) * (EBX + 2);
    for (int idx = tid; idx < NLOAD; idx += EBX * EBY) {
        int lx = idx % (EBX + 2);
        int ly = idx / (EBX + 2);
        int gx = min(max(tx0 - 1 + lx, 0), SW - 1);
        int gy = min(max(ty0 - 1 + ly, 0), SH - 1);
        s[ly][lx] = pl[gy * SW + gx];
    }
    __syncthreads();

    int lx = threadIdx.x, ly = threadIdx.y;
    float a = s[ly][lx],     bb = s[ly][lx + 1],     c = s[ly][lx + 2];
    float d = s[ly + 1][lx],                          f = s[ly + 1][lx + 2];
    float gg = s[ly + 2][lx], h = s[ly + 2][lx + 1], ii = s[ly + 2][lx + 2];

    float ch0m = SX2 * (c - a), ch0c = SX2 * (f - d), ch0p = SX2 * (ii - gg);
    float xg = 0.125f * (SY2 * (ch0m + ch0p) + (4.0f - 2.0f * SY2) * ch0c);
    float ch1m = SX2 * (a + c) + (4.0f - 2.0f * SX2) * bb;
    float ch1p = SX2 * (gg + ii) + (4.0f - 2.0f * SX2) * h;
    float yg = 0.125f * SY2 * (ch1p - ch1m);

    out[(b * SH + ty0 + ly) * SW + tx0 + lx] = make_float2(xg, yg);
}

// ---------------------------------------------------------------------------
// Bilinear upsample grad field 540x960 -> 1080x1920, 2 px/thread, half2 out
// ---------------------------------------------------------------------------
__global__ void k_upsample(const float2* __restrict__ gs, __half2* __restrict__ gf) {
    int i = blockIdx.x * blockDim.x + threadIdx.x;
    const int HALFW = IW / 2;
    if (i >= BATCH * IH * HALFW) return;
    int xp = (i % HALFW) * 2;
    int y  = (i / HALFW) % IH;
    int b  = i / (HALFW * IH);

    float fy = (float)y * (539.0f / 1079.0f);
    int y0 = min((int)fy, SH - 1);
    int y1 = min(y0 + 1, SH - 1);
    float wy = fy - (float)y0;

    const float2* p0 = gs + b * SH * SW + y0 * SW;
    const float2* p1 = gs + b * SH * SW + y1 * SW;

    __half2 res[2];
    #pragma unroll
    for (int k = 0; k < 2; ++k) {
        int x = xp + k;
        float fx = (float)x * (959.0f / 1919.0f);
        int x0 = min((int)fx, SW - 1);
        int x1 = min(x0 + 1, SW - 1);
        float wx = fx - (float)x0;
        float2 a00 = p0[x0], a01 = p0[x1], a10 = p1[x0], a11 = p1[x1];
        float vx = (a00.x * (1.0f - wx) + a01.x * wx) * (1.0f - wy)
                 + (a10.x * (1.0f - wx) + a11.x * wx) * wy;
        float vy = (a00.y * (1.0f - wx) + a01.y * wx) * (1.0f - wy)
                 + (a10.y * (1.0f - wx) + a11.y * wx) * wy;
        res[k] = __floats2half2_rn(vx, vy);
    }
    // one 8B coalesced store for 2 half2 values (xp even)
    *(uint2*)(gf + (size_t)(b * IH + y) * IW + xp) =
        make_uint2(*(unsigned*)&res[0], *(unsigned*)&res[1]);
}

// ---------------------------------------------------------------------------
// Warp: 6 fixed-point iterations + final image sample. 2 px/thread.
// ---------------------------------------------------------------------------
__global__ void k_warp(const float* __restrict__ img, const __half2* __restrict__ gf,
                       float* __restrict__ out) {
    int i = blockIdx.x * blockDim.x + threadIdx.x;
    const int HALFW = IW / 2;
    if (i >= BATCH * IH * HALFW) return;
    int Xp = (i % HALFW) * 2;
    int Y  = (i / HALFW) % IH;
    int b  = i / (HALFW * IH);

    const float relstr = ((float)IH / 1080.0f) * 0.1f;
    const float stepx = 2.0f / (float)IW * relstr;
    const float stepy = 2.0f / (float)IH * relstr;

    const __half2* g = gf + (size_t)b * IH * IW;

    float px[2], py[2];
    #pragma unroll
    for (int k = 0; k < 2; ++k) {
        px[k] = -1.0f + 2.0f * (float)(Xp + k) / (float)(IW - 1);
        py[k] = -1.0f + 2.0f * (float)Y / (float)(IH - 1);
    }

    #pragma unroll
    for (int it = 0; it < 6; ++it) {
        #pragma unroll
        for (int k = 0; k < 2; ++k) {
            float fx = clampf((px[k] + 1.0f) * 0.5f * (float)(IW - 1), 0.0f, (float)(IW - 1));
            float fy = clampf((py[k] + 1.0f) * 0.5f * (float)(IH - 1), 0.0f, (float)(IH - 1));
            int x0 = (int)fx, y0 = (int)fy;
            int x1 = min(x0 + 1, IW - 1), y1 = min(y0 + 1, IH - 1);
            float wx = fx - (float)x0, wy = fy - (float)y0;

            float2 a00 = __half22float2(g[y0 * IW + x0]);
            float2 a01 = __half22float2(g[y0 * IW + x1]);
            float2 a10 = __half22float2(g[y1 * IW + x0]);
            float2 a11 = __half22float2(g[y1 * IW + x1]);
            float dx = (a00.x * (1.0f - wx) + a01.x * wx) * (1.0f - wy)
                     + (a10.x * (1.0f - wx) + a11.x * wx) * wy;
            float dy = (a00.y * (1.0f - wx) + a01.y * wx) * (1.0f - wy)
                     + (a10.y * (1.0f - wx) + a11.y * wx) * wy;

            float len = sqrtf(dx * dx + dy * dy) + 0.01f;
            float inv = __fdividef(1.0f, len);
            px[k] -= dx * inv * stepx;
            py[k] -= dy * inv * stepy;
        }
    }

    int o00[2], o01[2], o10[2], o11[2];
    float wx[2], wy[2];
    #pragma unroll
    for (int k = 0; k < 2; ++k) {
        float fx = clampf((px[k] + 1.0f) * 0.5f * (float)(IW - 1), 0.0f, (float)(IW - 1));
        float fy = clampf((py[k] + 1.0f) * 0.5f * (float)(IH - 1), 0.0f, (float)(IH - 1));
        int x0 = (int)fx, y0 = (int)fy;
        int x1 = min(x0 + 1, IW - 1), y1 = min(y0 + 1, IH - 1);
        wx[k] = fx - (float)x0; wy[k] = fy - (float)y0;
        o00[k] = y0 * IW + x0; o01[k] = y0 * IW + x1;
        o10[k] = y1 * IW + x0; o11[k] = y1 * IW + x1;
    }

    #pragma unroll
    for (int c = 0; c < 3; ++c) {
        const float* p = img + ((size_t)b * 3 + c) * IH * IW;
        float v[2];
        #pragma unroll
        for (int k = 0; k < 2; ++k) {
            float vv = (p[o00[k]] * (1.0f - wx[k]) + p[o01[k]] * wx[k]) * (1.0f - wy[k])
                     + (p[o10[k]] * (1.0f - wx[k]) + p[o11[k]] * wx[k]) * wy[k];
            v[k] = clampf(vv, 0.0f, 1.0f);
        }
        float2* dst = (float2*)(out + ((size_t)b * 3 + c) * IH * IW + (size_t)Y * IW + Xp);
        *dst = make_float2(v[0], v[1]);
    }
}

// ---------------------------------------------------------------------------
extern "C" void kernel_launch(void* const* d_in, const int* in_sizes, int n_in,
                              void* d_out, int out_size) {
    const float* img = (const float*)d_in[0];
    float* out = (float*)d_out;

    float *p_edge, *p_tmp;
    float2 *p_grad_s;
    __half2 *p_grad_f;
    cudaGetSymbolAddress((void**)&p_edge, g_edge);
    cudaGetSymbolAddress((void**)&p_tmp, g_tmp);
    cudaGetSymbolAddress((void**)&p_grad_s, g_grad_s);
    cudaGetSymbolAddress((void**)&p_grad_f, g_grad_f);

    dim3 eb(EBX, EBY);
    dim3 eg(SW / EBX, SH / EBY, BATCH);       // 30 x 30 x 2
    k_luma_edge<<<eg, eb>>>(img, p_edge);

    dim3 bb(BBX, BBY);
    dim3 gb(SW / BBX, SH / BBY, BATCH);
    k_blur<<<gb, bb>>>(p_edge, p_tmp);

    k_grad<<<eg, eb>>>(p_tmp, p_grad_s);

    const int T = 256;
    int gh = (BATCH * IH * (IW / 2) + T - 1) / T;
    k_upsample<<<gh, T>>>(p_grad_s, p_grad_f);
    k_warp<<<gh, T>>>(img, p_grad_f, out);
}

// round 5
// speedup vs baseline: 1.3641x; 1.1397x over previous
#include <cuda_runtime.h>
#include <math.h>

#define BATCH 2
#define IH 1080
#define IW 1920
#define SH 540
#define SW 960

#define N_SMALL (BATCH * SH * SW)

// sobel pixel shifts (compile-time): offset*(W-1)/W, offset*(H-1)/H
#define SX1 (959.0f / 960.0f)
#define SY1 (539.0f / 540.0f)
#define SX2 (0.5f * 959.0f / 960.0f)
#define SY2 (0.5f * 539.0f / 540.0f)

// Gaussian sigma=1.0, ks=5 weights
#define GW0 0.05448868f
#define GW1 0.24420135f
#define GW2 0.40261995f

// Scratch (allocation-free: __device__ globals)
__device__ float  g_edge[N_SMALL];         // edge magnitude
__device__ float  g_tmp[N_SMALL];          // blurred edge
__device__ float2 g_grad_s[N_SMALL];       // coarse gradient field (xg, yg)

__device__ __forceinline__ float clampf(float v, float lo, float hi) {
    return fminf(fmaxf(v, lo), hi);
}

// ---------------------------------------------------------------------------
// Fused: luma + bilinear downscale + sobel(offset=1) edge magnitude.
// ---------------------------------------------------------------------------
#define EBX 32
#define EBY 18
__global__ void k_luma_edge(const float* __restrict__ img, float* __restrict__ out) {
    __shared__ float s[EBY + 2][EBX + 2];
    int b = blockIdx.z;
    int tx0 = blockIdx.x * EBX;
    int ty0 = blockIdx.y * EBY;

    const float* r  = img + ((size_t)b * 3 + 0) * IH * IW;
    const float* g  = img + ((size_t)b * 3 + 1) * IH * IW;
    const float* bl = img + ((size_t)b * 3 + 2) * IH * IW;

    int tid = threadIdx.y * EBX + threadIdx.x;
    const int NLOAD = (EBY + 2) * (EBX + 2);
    for (int idx = tid; idx < NLOAD; idx += EBX * EBY) {
        int lx = idx % (EBX + 2);
        int ly = idx / (EBX + 2);
        int xs = min(max(tx0 - 1 + lx, 0), SW - 1);
        int ys = min(max(ty0 - 1 + ly, 0), SH - 1);
        float fx = (float)xs * (1919.0f / 959.0f);
        float fy = (float)ys * (1079.0f / 539.0f);
        int x0 = min((int)fx, IW - 1); int x1 = min(x0 + 1, IW - 1);
        int y0 = min((int)fy, IH - 1); int y1 = min(y0 + 1, IH - 1);
        float wx = fx - (float)x0, wy = fy - (float)y0;
        int o00 = y0 * IW + x0, o01 = y0 * IW + x1, o10 = y1 * IW + x0, o11 = y1 * IW + x1;
        float v00 = 0.299f * r[o00] + 0.587f * g[o00] + 0.114f * bl[o00];
        float v01 = 0.299f * r[o01] + 0.587f * g[o01] + 0.114f * bl[o01];
        float v10 = 0.299f * r[o10] + 0.587f * g[o10] + 0.114f * bl[o10];
        float v11 = 0.299f * r[o11] + 0.587f * g[o11] + 0.114f * bl[o11];
        s[ly][lx] = (v00 * (1.0f - wx) + v01 * wx) * (1.0f - wy)
                  + (v10 * (1.0f - wx) + v11 * wx) * wy;
    }
    __syncthreads();

    int lx = threadIdx.x, ly = threadIdx.y;
    float a = s[ly][lx],     bb = s[ly][lx + 1],     c = s[ly][lx + 2];
    float d = s[ly + 1][lx],                          f = s[ly + 1][lx + 2];
    float gg = s[ly + 2][lx], h = s[ly + 2][lx + 1], ii = s[ly + 2][lx + 2];

    float ch0m = SX1 * (c - a), ch0c = SX1 * (f - d), ch0p = SX1 * (ii - gg);
    float xg = 0.125f * (SY1 * (ch0m + ch0p) + (4.0f - 2.0f * SY1) * ch0c);
    float ch1m = SX1 * (a + c) + (4.0f - 2.0f * SX1) * bb;
    float ch1p = SX1 * (gg + ii) + (4.0f - 2.0f * SX1) * h;
    float yg = 0.125f * SY1 * (ch1p - ch1m);

    out[(b * SH + ty0 + ly) * SW + tx0 + lx] = powf(xg * xg + yg * yg, 0.35f);
}

// ---------------------------------------------------------------------------
// Fused separable Gaussian blur (5x5 outer-product, edge replicate)
// ---------------------------------------------------------------------------
#define BBX 32
#define BBY 10
__global__ void k_blur(const float* __restrict__ in, float* __restrict__ out) {
    __shared__ float s[BBY + 4][BBX + 4];
    int b = blockIdx.z;
    int tx0 = blockIdx.x * BBX;
    int ty0 = blockIdx.y * BBY;
    const float* pl = in + b * SH * SW;

    int tid = threadIdx.y * BBX + threadIdx.x;
    const int NLOAD = (BBY + 4) * (BBX + 4);
    for (int idx = tid; idx < NLOAD; idx += BBX * BBY) {
        int lx = idx % (BBX + 4);
        int ly = idx / (BBX + 4);
        int gx = min(max(tx0 - 2 + lx, 0), SW - 1);
        int gy = min(max(ty0 - 2 + ly, 0), SH - 1);
        s[ly][lx] = pl[gy * SW + gx];
    }
    __syncthreads();

    int lx = threadIdx.x, ly = threadIdx.y;
    const float w[5] = {GW0, GW1, GW2, GW1, GW0};
    float acc = 0.0f;
    #pragma unroll
    for (int j = 0; j < 5; ++j) {
        float h = 0.0f;
        #pragma unroll
        for (int ii = 0; ii < 5; ++ii)
            h = fmaf(w[ii], s[ly + j][lx + ii], h);
        acc = fmaf(w[j], h, acc);
    }
    out[(b * SH + ty0 + ly) * SW + tx0 + lx] = acc;
}

// ---------------------------------------------------------------------------
// sobel(offset=0.5) gradient field: constant-weight 3x3 stencil (smem tile)
// ---------------------------------------------------------------------------
__global__ void k_grad(const float* __restrict__ in, float2* __restrict__ out) {
    __shared__ float s[EBY + 2][EBX + 2];
    int b = blockIdx.z;
    int tx0 = blockIdx.x * EBX;
    int ty0 = blockIdx.y * EBY;
    const float* pl = in + b * SH * SW;

    int tid = threadIdx.y * EBX + threadIdx.x;
    const int NLOAD = (EBY + 2) * (EBX + 2);
    for (int idx = tid; idx < NLOAD; idx += EBX * EBY) {
        int lx = idx % (EBX + 2);
        int ly = idx / (EBX + 2);
        int gx = min(max(tx0 - 1 + lx, 0), SW - 1);
        int gy = min(max(ty0 - 1 + ly, 0), SH - 1);
        s[ly][lx] = pl[gy * SW + gx];
    }
    __syncthreads();

    int lx = threadIdx.x, ly = threadIdx.y;
    float a = s[ly][lx],     bb = s[ly][lx + 1],     c = s[ly][lx + 2];
    float d = s[ly + 1][lx],                          f = s[ly + 1][lx + 2];
    float gg = s[ly + 2][lx], h = s[ly + 2][lx + 1], ii = s[ly + 2][lx + 2];

    float ch0m = SX2 * (c - a), ch0c = SX2 * (f - d), ch0p = SX2 * (ii - gg);
    float xg = 0.125f * (SY2 * (ch0m + ch0p) + (4.0f - 2.0f * SY2) * ch0c);
    float ch1m = SX2 * (a + c) + (4.0f - 2.0f * SX2) * bb;
    float ch1p = SX2 * (gg + ii) + (4.0f - 2.0f * SX2) * h;
    float yg = 0.125f * SY2 * (ch1p - ch1m);

    out[(b * SH + ty0 + ly) * SW + tx0 + lx] = make_float2(xg, yg);
}

// ---------------------------------------------------------------------------
// Fused upsample + warp. Key fact: total warp displacement <= 0.6 px, so all
// gradient-field and image taps lie within [X-1, X+1] x [Y-1, Y+1] of the
// starting pixel. A 32x8 tile + halo 1 (34x10) in smem covers everything.
// The full-res gradient tile is computed on the fly from the coarse field
// (identical formula to the former k_upsample -> identical values).
// Halo clamping in the tile load replicates the border, which reproduces
// x1 = min(x0+1, W-1) exactly.
// ---------------------------------------------------------------------------
#define WBX 32
#define WBY 8
#define TW (WBX + 2)   // 34
#define TH (WBY + 2)   // 10
__global__ void k_warp(const float* __restrict__ img, const float2* __restrict__ gs,
                       float* __restrict__ out) {
    __shared__ float2 s_g[TH][TW];
    __shared__ float  s_im[3][TH][TW];

    int b  = blockIdx.z;
    int X0 = blockIdx.x * WBX;
    int Y0 = blockIdx.y * WBY;

    const float2* gsb  = gs + b * SH * SW;
    const float*  imgb = img + (size_t)b * 3 * IH * IW;

    int tid = threadIdx.y * WBX + threadIdx.x;
    for (int idx = tid; idx < TW * TH; idx += WBX * WBY) {
        int lx = idx % TW;
        int ly = idx / TW;
        int gx = min(max(X0 - 1 + lx, 0), IW - 1);
        int gy = min(max(Y0 - 1 + ly, 0), IH - 1);

        // on-the-fly bilinear upsample of the coarse gradient field
        float fx = (float)gx * (959.0f / 1919.0f);
        float fy = (float)gy * (539.0f / 1079.0f);
        int x0 = min((int)fx, SW - 1); int x1 = min(x0 + 1, SW - 1);
        int y0 = min((int)fy, SH - 1); int y1 = min(y0 + 1, SH - 1);
        float wx = fx - (float)x0, wy = fy - (float)y0;
        float2 a00 = gsb[y0 * SW + x0], a01 = gsb[y0 * SW + x1];
        float2 a10 = gsb[y1 * SW + x0], a11 = gsb[y1 * SW + x1];
        float vx = (a00.x * (1.0f - wx) + a01.x * wx) * (1.0f - wy)
                 + (a10.x * (1.0f - wx) + a11.x * wx) * wy;
        float vy = (a00.y * (1.0f - wx) + a01.y * wx) * (1.0f - wy)
                 + (a10.y * (1.0f - wx) + a11.y * wx) * wy;
        s_g[ly][lx] = make_float2(vx, vy);

        int off = gy * IW + gx;
        s_im[0][ly][lx] = imgb[off];
        s_im[1][ly][lx] = imgb[IH * IW + off];
        s_im[2][ly][lx] = imgb[2 * IH * IW + off];
    }
    __syncthreads();

    int X = X0 + threadIdx.x;
    int Y = Y0 + threadIdx.y;

    const float relstr = ((float)IH / 1080.0f) * 0.1f;
    const float stepx = 2.0f / (float)IW * relstr;
    const float stepy = 2.0f / (float)IH * relstr;

    float px = -1.0f + 2.0f * (float)X / (float)(IW - 1);
    float py = -1.0f + 2.0f * (float)Y / (float)(IH - 1);

    const float cx = (float)(X0 - 1);   // tile origin (global col of lx=0)
    const float cy = (float)(Y0 - 1);

    #pragma unroll
    for (int it = 0; it < 6; ++it) {
        float fx = clampf((px + 1.0f) * 0.5f * (float)(IW - 1), 0.0f, (float)(IW - 1));
        float fy = clampf((py + 1.0f) * 0.5f * (float)(IH - 1), 0.0f, (float)(IH - 1));
        // tile-relative (exact: subtracting small ints from float is exact here)
        float tx = fx - cx, ty = fy - cy;
        int x0 = (int)tx, y0 = (int)ty;
        float wx = tx - (float)x0, wy = ty - (float)y0;

        float2 a00 = s_g[y0][x0],     a01 = s_g[y0][x0 + 1];
        float2 a10 = s_g[y0 + 1][x0], a11 = s_g[y0 + 1][x0 + 1];
        float dx = (a00.x * (1.0f - wx) + a01.x * wx) * (1.0f - wy)
                 + (a10.x * (1.0f - wx) + a11.x * wx) * wy;
        float dy = (a00.y * (1.0f - wx) + a01.y * wx) * (1.0f - wy)
                 + (a10.y * (1.0f - wx) + a11.y * wx) * wy;

        float len = sqrtf(dx * dx + dy * dy) + 0.01f;
        float inv = __fdividef(1.0f, len);
        px -= dx * inv * stepx;
        py -= dy * inv * stepy;
    }

    float fx = clampf((px + 1.0f) * 0.5f * (float)(IW - 1), 0.0f, (float)(IW - 1));
    float fy = clampf((py + 1.0f) * 0.5f * (float)(IH - 1), 0.0f, (float)(IH - 1));
    float tx = fx - cx, ty = fy - cy;
    int x0 = (int)tx, y0 = (int)ty;
    float wx = tx - (float)x0, wy = ty - (float)y0;

    size_t obase = (size_t)b * 3 * IH * IW + (size_t)Y * IW + X;
    #pragma unroll
    for (int c = 0; c < 3; ++c) {
        float v = (s_im[c][y0][x0] * (1.0f - wx) + s_im[c][y0][x0 + 1] * wx) * (1.0f - wy)
                + (s_im[c][y0 + 1][x0] * (1.0f - wx) + s_im[c][y0 + 1][x0 + 1] * wx) * wy;
        out[obase + (size_t)c * IH * IW] = clampf(v, 0.0f, 1.0f);
    }
}

// ---------------------------------------------------------------------------
extern "C" void kernel_launch(void* const* d_in, const int* in_sizes, int n_in,
                              void* d_out, int out_size) {
    const float* img = (const float*)d_in[0];
    float* out = (float*)d_out;

    float *p_edge, *p_tmp;
    float2 *p_grad_s;
    cudaGetSymbolAddress((void**)&p_edge, g_edge);
    cudaGetSymbolAddress((void**)&p_tmp, g_tmp);
    cudaGetSymbolAddress((void**)&p_grad_s, g_grad_s);

    dim3 eb(EBX, EBY);
    dim3 eg(SW / EBX, SH / EBY, BATCH);       // 30 x 30 x 2
    k_luma_edge<<<eg, eb>>>(img, p_edge);

    dim3 bb(BBX, BBY);
    dim3 gb(SW / BBX, SH / BBY, BATCH);
    k_blur<<<gb, bb>>>(p_edge, p_tmp);

    k_grad<<<eg, eb>>>(p_tmp, p_grad_s);

    dim3 wb(WBX, WBY);
    dim3 wg(IW / WBX, IH / WBY, BATCH);       // 60 x 135 x 2
    k_warp<<<wg, wb>>>(img, p_grad_s, out);
}

// round 6
// speedup vs baseline: 1.3649x; 1.0005x over previous
#include <cuda_runtime.h>
#include <math.h>

#define BATCH 2
#define IH 1080
#define IW 1920
#define SH 540
#define SW 960

#define N_SMALL (BATCH * SH * SW)

// sobel pixel shifts (compile-time): offset*(W-1)/W, offset*(H-1)/H
#define SX1 (959.0f / 960.0f)
#define SY1 (539.0f / 540.0f)
#define SX2 (0.5f * 959.0f / 960.0f)
#define SY2 (0.5f * 539.0f / 540.0f)

// Gaussian sigma=1.0, ks=5 weights
#define GW0 0.05448868f
#define GW1 0.24420135f
#define GW2 0.40261995f

// Scratch (allocation-free: __device__ globals)
__device__ float  g_edge[N_SMALL];         // edge magnitude
__device__ float  g_tmp[N_SMALL];          // blurred edge
__device__ float2 g_grad_s[N_SMALL];       // coarse gradient field (xg, yg)

__device__ __forceinline__ float clampf(float v, float lo, float hi) {
    return fminf(fmaxf(v, lo), hi);
}

// ---------------------------------------------------------------------------
// Fused: luma + bilinear downscale + sobel(offset=1) edge magnitude.
// ---------------------------------------------------------------------------
#define EBX 32
#define EBY 18
__global__ void k_luma_edge(const float* __restrict__ img, float* __restrict__ out) {
    __shared__ float s[EBY + 2][EBX + 2];
    int b = blockIdx.z;
    int tx0 = blockIdx.x * EBX;
    int ty0 = blockIdx.y * EBY;

    const float* r  = img + ((size_t)b * 3 + 0) * IH * IW;
    const float* g  = img + ((size_t)b * 3 + 1) * IH * IW;
    const float* bl = img + ((size_t)b * 3 + 2) * IH * IW;

    int tid = threadIdx.y * EBX + threadIdx.x;
    const int NLOAD = (EBY + 2) * (EBX + 2);
    for (int idx = tid; idx < NLOAD; idx += EBX * EBY) {
        int lx = idx % (EBX + 2);
        int ly = idx / (EBX + 2);
        int xs = min(max(tx0 - 1 + lx, 0), SW - 1);
        int ys = min(max(ty0 - 1 + ly, 0), SH - 1);
        float fx = (float)xs * (1919.0f / 959.0f);
        float fy = (float)ys * (1079.0f / 539.0f);
        int x0 = min((int)fx, IW - 1); int x1 = min(x0 + 1, IW - 1);
        int y0 = min((int)fy, IH - 1); int y1 = min(y0 + 1, IH - 1);
        float wx = fx - (float)x0, wy = fy - (float)y0;
        int o00 = y0 * IW + x0, o01 = y0 * IW + x1, o10 = y1 * IW + x0, o11 = y1 * IW + x1;
        float v00 = 0.299f * r[o00] + 0.587f * g[o00] + 0.114f * bl[o00];
        float v01 = 0.299f * r[o01] + 0.587f * g[o01] + 0.114f * bl[o01];
        float v10 = 0.299f * r[o10] + 0.587f * g[o10] + 0.114f * bl[o10];
        float v11 = 0.299f * r[o11] + 0.587f * g[o11] + 0.114f * bl[o11];
        s[ly][lx] = (v00 * (1.0f - wx) + v01 * wx) * (1.0f - wy)
                  + (v10 * (1.0f - wx) + v11 * wx) * wy;
    }
    __syncthreads();

    int lx = threadIdx.x, ly = threadIdx.y;
    float a = s[ly][lx],     bb = s[ly][lx + 1],     c = s[ly][lx + 2];
    float d = s[ly + 1][lx],                          f = s[ly + 1][lx + 2];
    float gg = s[ly + 2][lx], h = s[ly + 2][lx + 1], ii = s[ly + 2][lx + 2];

    float ch0m = SX1 * (c - a), ch0c = SX1 * (f - d), ch0p = SX1 * (ii - gg);
    float xg = 0.125f * (SY1 * (ch0m + ch0p) + (4.0f - 2.0f * SY1) * ch0c);
    float ch1m = SX1 * (a + c) + (4.0f - 2.0f * SX1) * bb;
    float ch1p = SX1 * (gg + ii) + (4.0f - 2.0f * SX1) * h;
    float yg = 0.125f * SY1 * (ch1p - ch1m);

    out[(b * SH + ty0 + ly) * SW + tx0 + lx] = powf(xg * xg + yg * yg, 0.35f);
}

// ---------------------------------------------------------------------------
// Fused separable Gaussian blur (5x5 outer-product, edge replicate)
// ---------------------------------------------------------------------------
#define BBX 32
#define BBY 10
__global__ void k_blur(const float* __restrict__ in, float* __restrict__ out) {
    __shared__ float s[BBY + 4][BBX + 4];
    int b = blockIdx.z;
    int tx0 = blockIdx.x * BBX;
    int ty0 = blockIdx.y * BBY;
    const float* pl = in + b * SH * SW;

    int tid = threadIdx.y * BBX + threadIdx.x;
    const int NLOAD = (BBY + 4) * (BBX + 4);
    for (int idx = tid; idx < NLOAD; idx += BBX * BBY) {
        int lx = idx % (BBX + 4);
        int ly = idx / (BBX + 4);
        int gx = min(max(tx0 - 2 + lx, 0), SW - 1);
        int gy = min(max(ty0 - 2 + ly, 0), SH - 1);
        s[ly][lx] = pl[gy * SW + gx];
    }
    __syncthreads();

    int lx = threadIdx.x, ly = threadIdx.y;
    const float w[5] = {GW0, GW1, GW2, GW1, GW0};
    float acc = 0.0f;
    #pragma unroll
    for (int j = 0; j < 5; ++j) {
        float h = 0.0f;
        #pragma unroll
        for (int ii = 0; ii < 5; ++ii)
            h = fmaf(w[ii], s[ly + j][lx + ii], h);
        acc = fmaf(w[j], h, acc);
    }
    out[(b * SH + ty0 + ly) * SW + tx0 + lx] = acc;
}

// ---------------------------------------------------------------------------
// sobel(offset=0.5) gradient field: constant-weight 3x3 stencil (smem tile)
// ---------------------------------------------------------------------------
__global__ void k_grad(const float* __restrict__ in, float2* __restrict__ out) {
    __shared__ float s[EBY + 2][EBX + 2];
    int b = blockIdx.z;
    int tx0 = blockIdx.x * EBX;
    int ty0 = blockIdx.y * EBY;
    const float* pl = in + b * SH * SW;

    int tid = threadIdx.y * EBX + threadIdx.x;
    const int NLOAD = (EBY + 2) * (EBX + 2);
    for (int idx = tid; idx < NLOAD; idx += EBX * EBY) {
        int lx = idx % (EBX + 2);
        int ly = idx / (EBX + 2);
        int gx = min(max(tx0 - 1 + lx, 0), SW - 1);
        int gy = min(max(ty0 - 1 + ly, 0), SH - 1);
        s[ly][lx] = pl[gy * SW + gx];
    }
    __syncthreads();

    int lx = threadIdx.x, ly = threadIdx.y;
    float a = s[ly][lx],     bb = s[ly][lx + 1],     c = s[ly][lx + 2];
    float d = s[ly + 1][lx],                          f = s[ly + 1][lx + 2];
    float gg = s[ly + 2][lx], h = s[ly + 2][lx + 1], ii = s[ly + 2][lx + 2];

    float ch0m = SX2 * (c - a), ch0c = SX2 * (f - d), ch0p = SX2 * (ii - gg);
    float xg = 0.125f * (SY2 * (ch0m + ch0p) + (4.0f - 2.0f * SY2) * ch0c);
    float ch1m = SX2 * (a + c) + (4.0f - 2.0f * SX2) * bb;
    float ch1p = SX2 * (gg + ii) + (4.0f - 2.0f * SX2) * h;
    float yg = 0.125f * SY2 * (ch1p - ch1m);

    out[(b * SH + ty0 + ly) * SW + tx0 + lx] = make_float2(xg, yg);
}

// ---------------------------------------------------------------------------
// Fused upsample + warp. Key fact: total warp displacement <= 0.6 px, so all
// gradient-field and image taps lie within [X-1, X+1] x [Y-1, Y+1] of the
// starting pixel. A 32x8 tile + halo 1 (34x10) in smem covers everything.
// The full-res gradient tile is computed on the fly from the coarse field
// (identical formula to the former k_upsample -> identical values).
// Halo clamping in the tile load replicates the border, which reproduces
// x1 = min(x0+1, W-1) exactly.
// ---------------------------------------------------------------------------
#define WBX 32
#define WBY 8
#define TW (WBX + 2)   // 34
#define TH (WBY + 2)   // 10
__global__ void k_warp(const float* __restrict__ img, const float2* __restrict__ gs,
                       float* __restrict__ out) {
    __shared__ float2 s_g[TH][TW];
    __shared__ float  s_im[3][TH][TW];

    int b  = blockIdx.z;
    int X0 = blockIdx.x * WBX;
    int Y0 = blockIdx.y * WBY;

    const float2* gsb  = gs + b * SH * SW;
    const float*  imgb = img + (size_t)b * 3 * IH * IW;

    int tid = threadIdx.y * WBX + threadIdx.x;
    for (int idx = tid; idx < TW * TH; idx += WBX * WBY) {
        int lx = idx % TW;
        int ly = idx / TW;
        int gx = min(max(X0 - 1 + lx, 0), IW - 1);
        int gy = min(max(Y0 - 1 + ly, 0), IH - 1);

        // on-the-fly bilinear upsample of the coarse gradient field
        float fx = (float)gx * (959.0f / 1919.0f);
        float fy = (float)gy * (539.0f / 1079.0f);
        int x0 = min((int)fx, SW - 1); int x1 = min(x0 + 1, SW - 1);
        int y0 = min((int)fy, SH - 1); int y1 = min(y0 + 1, SH - 1);
        float wx = fx - (float)x0, wy = fy - (float)y0;
        float2 a00 = gsb[y0 * SW + x0], a01 = gsb[y0 * SW + x1];
        float2 a10 = gsb[y1 * SW + x0], a11 = gsb[y1 * SW + x1];
        float vx = (a00.x * (1.0f - wx) + a01.x * wx) * (1.0f - wy)
                 + (a10.x * (1.0f - wx) + a11.x * wx) * wy;
        float vy = (a00.y * (1.0f - wx) + a01.y * wx) * (1.0f - wy)
                 + (a10.y * (1.0f - wx) + a11.y * wx) * wy;
        s_g[ly][lx] = make_float2(vx, vy);

        int off = gy * IW + gx;
        s_im[0][ly][lx] = imgb[off];
        s_im[1][ly][lx] = imgb[IH * IW + off];
        s_im[2][ly][lx] = imgb[2 * IH * IW + off];
    }
    __syncthreads();

    int X = X0 + threadIdx.x;
    int Y = Y0 + threadIdx.y;

    const float relstr = ((float)IH / 1080.0f) * 0.1f;
    const float stepx = 2.0f / (float)IW * relstr;
    const float stepy = 2.0f / (float)IH * relstr;

    float px = -1.0f + 2.0f * (float)X / (float)(IW - 1);
    float py = -1.0f + 2.0f * (float)Y / (float)(IH - 1);

    const float cx = (float)(X0 - 1);   // tile origin (global col of lx=0)
    const float cy = (float)(Y0 - 1);

    #pragma unroll
    for (int it = 0; it < 6; ++it) {
        float fx = clampf((px + 1.0f) * 0.5f * (float)(IW - 1), 0.0f, (float)(IW - 1));
        float fy = clampf((py + 1.0f) * 0.5f * (float)(IH - 1), 0.0f, (float)(IH - 1));
        // tile-relative (exact: subtracting small ints from float is exact here)
        float tx = fx - cx, ty = fy - cy;
        int x0 = (int)tx, y0 = (int)ty;
        float wx = tx - (float)x0, wy = ty - (float)y0;

        float2 a00 = s_g[y0][x0],     a01 = s_g[y0][x0 + 1];
        float2 a10 = s_g[y0 + 1][x0], a11 = s_g[y0 + 1][x0 + 1];
        float dx = (a00.x * (1.0f - wx) + a01.x * wx) * (1.0f - wy)
                 + (a10.x * (1.0f - wx) + a11.x * wx) * wy;
        float dy = (a00.y * (1.0f - wx) + a01.y * wx) * (1.0f - wy)
                 + (a10.y * (1.0f - wx) + a11.y * wx) * wy;

        float len = sqrtf(dx * dx + dy * dy) + 0.01f;
        float inv = __fdividef(1.0f, len);
        px -= dx * inv * stepx;
        py -= dy * inv * stepy;
    }

    float fx = clampf((px + 1.0f) * 0.5f * (float)(IW - 1), 0.0f, (float)(IW - 1));
    float fy = clampf((py + 1.0f) * 0.5f * (float)(IH - 1), 0.0f, (float)(IH - 1));
    float tx = fx - cx, ty = fy - cy;
    int x0 = (int)tx, y0 = (int)ty;
    float wx = tx - (float)x0, wy = ty - (float)y0;

    size_t obase = (size_t)b * 3 * IH * IW + (size_t)Y * IW + X;
    #pragma unroll
    for (int c = 0; c < 3; ++c) {
        float v = (s_im[c][y0][x0] * (1.0f - wx) + s_im[c][y0][x0 + 1] * wx) * (1.0f - wy)
                + (s_im[c][y0 + 1][x0] * (1.0f - wx) + s_im[c][y0 + 1][x0 + 1] * wx) * wy;
        out[obase + (size_t)c * IH * IW] = clampf(v, 0.0f, 1.0f);
    }
}

// ---------------------------------------------------------------------------
extern "C" void kernel_launch(void* const* d_in, const int* in_sizes, int n_in,
                              void* d_out, int out_size) {
    const float* img = (const float*)d_in[0];
    float* out = (float*)d_out;

    float *p_edge, *p_tmp;
    float2 *p_grad_s;
    cudaGetSymbolAddress((void**)&p_edge, g_edge);
    cudaGetSymbolAddress((void**)&p_tmp, g_tmp);
    cudaGetSymbolAddress((void**)&p_grad_s, g_grad_s);

    dim3 eb(EBX, EBY);
    dim3 eg(SW / EBX, SH / EBY, BATCH);       // 30 x 30 x 2
    k_luma_edge<<<eg, eb>>>(img, p_edge);

    dim3 bb(BBX, BBY);
    dim3 gb(SW / BBX, SH / BBY, BATCH);
    k_blur<<<gb, bb>>>(p_edge, p_tmp);

    k_grad<<<eg, eb>>>(p_tmp, p_grad_s);

    dim3 wb(WBX, WBY);
    dim3 wg(IW / WBX, IH / WBY, BATCH);       // 60 x 135 x 2
    k_warp<<<wg, wb>>>(img, p_grad_s, out);
}